// round 9
// baseline (speedup 1.0000x reference)
#include <cuda_runtime.h>
#include <cuda_bf16.h>
#include <stdint.h>

#define KCLS   64
#define QPC    128
#define DIMK   1024
#define NROWS  (KCLS * QPC)      // 8192
#define TMR    32                // rows per CTA
#define NCTA   (NROWS / TMR)     // 256
#define KC     128               // k elems per chunk
#define NCHUNK (DIMK / KC)       // 8 per modality

// ---------------- smem layout (bytes), stride-136 bf16 rows (272B) ----------
#define A_STR   136
#define OFF_AH  0
#define OFF_AL  8704                     // 32*136*2
#define OFF_BH  17408
#define OFF_BL  34816                    // + 64*136*2
#define BUFSZ   52224
#define OFF_SL  0                        // logits reuse buf0 (32 x 72 fp32)
#define SL_STR  72
#define OFF_SX2 (2 * BUFSZ)              // 104448
#define OFF_SP2 (OFF_SX2 + 128)
#define OFF_SRV (OFF_SP2 + 256)
#define OFF_RED (OFF_SRV + 256)          // sBLoss (f32), sBAcc (int)
#define SMEM_TOTAL (OFF_RED + 64)        // 105152

__device__ float2 g_part[NCTA];          // per-CTA (loss_sum, acc_count)

// ---------------------------------------------------------------------------
__device__ __forceinline__ uint32_t smem_u32(const void* p) {
    uint32_t a;
    asm("{ .reg .u64 t; cvta.to.shared.u64 t, %1; cvt.u32.u64 %0, t; }" : "=r"(a) : "l"(p));
    return a;
}
__device__ __forceinline__ void ldsm4(uint32_t* r, uint32_t a) {
    asm volatile("ldmatrix.sync.aligned.m8n8.x4.shared.b16 {%0,%1,%2,%3}, [%4];"
                 : "=r"(r[0]), "=r"(r[1]), "=r"(r[2]), "=r"(r[3]) : "r"(a));
}
__device__ __forceinline__ void ldsm2(uint32_t* r, uint32_t a) {
    asm volatile("ldmatrix.sync.aligned.m8n8.x2.shared.b16 {%0,%1}, [%2];"
                 : "=r"(r[0]), "=r"(r[1]) : "r"(a));
}
__device__ __forceinline__ void mma_bf16(float c[4], const uint32_t a[4], const uint32_t b[2]) {
    asm volatile(
        "mma.sync.aligned.m16n8k16.row.col.f32.bf16.bf16.f32 "
        "{%0,%1,%2,%3}, {%4,%5,%6,%7}, {%8,%9}, {%0,%1,%2,%3};\n"
        : "+f"(c[0]), "+f"(c[1]), "+f"(c[2]), "+f"(c[3])
        : "r"(a[0]), "r"(a[1]), "r"(a[2]), "r"(a[3]), "r"(b[0]), "r"(b[1]));
}

// fp32x8 -> bf16 hi + bf16 lo
__device__ __forceinline__ void split8(float4 a, float4 b, uint4& hi, uint4& lo) {
    float f[8] = {a.x, a.y, a.z, a.w, b.x, b.y, b.z, b.w};
    uint32_t hw[4], lw[4];
    #pragma unroll
    for (int i = 0; i < 4; i++) {
        __nv_bfloat162 h = __floats2bfloat162_rn(f[2*i], f[2*i+1]);
        float r0 = f[2*i]     - __bfloat162float(h.x);
        float r1 = f[2*i + 1] - __bfloat162float(h.y);
        __nv_bfloat162 l = __floats2bfloat162_rn(r0, r1);
        hw[i] = *reinterpret_cast<uint32_t*>(&h);
        lw[i] = *reinterpret_cast<uint32_t*>(&l);
    }
    hi = make_uint4(hw[0], hw[1], hw[2], hw[3]);
    lo = make_uint4(lw[0], lw[1], lw[2], lw[3]);
}
__device__ __forceinline__ float sq8(float4 a, float4 b) {
    return a.x*a.x + a.y*a.y + a.z*a.z + a.w*a.w
         + b.x*b.x + b.y*b.y + b.z*b.z + b.w*b.w;
}

// ---------------------------------------------------------------------------
// self-contained fused kernel: in-CTA B split + p2 + rvar, bf16 hi/lo-split
// HMMA GEMM, softmax, loss, argmax. grid 256 CTAs x 256 threads.
// ---------------------------------------------------------------------------
__global__ void __launch_bounds__(256, 2)
fusion_kernel(const float* __restrict__ xTF, const float* __restrict__ pTF, const float* __restrict__ vTF,
              const float* __restrict__ xDE, const float* __restrict__ pDE, const float* __restrict__ vDE,
              const float* __restrict__ xFFT, const float* __restrict__ pFFT, const float* __restrict__ vFFT)
{
    extern __shared__ unsigned char smemc[];
    const uint32_t sb = smem_u32(smemc);

    const int tid  = threadIdx.x;
    const int warp = tid >> 5;
    const int lane = tid & 31;
    const int gr   = lane >> 2;
    const int lk   = (lane & 3) * 2;
    const int cls  = (int)(blockIdx.x >> 2);
    const size_t rowbase = (size_t)blockIdx.x * TMR;

    // producer mappings
    const int arow  = tid >> 3;            // 0..31
    const int acseg = (tid & 7) * 16;      // fp32 col base (A), 16 floats
    const int brow  = tid >> 2;            // 0..63
    const int bcseg = (tid & 3) * 32;      // fp32 col base (B), 32 floats

    float* sL   = reinterpret_cast<float*>(smemc + OFF_SL);
    float* sX2  = reinterpret_cast<float*>(smemc + OFF_SX2);
    float* sP2  = reinterpret_cast<float*>(smemc + OFF_SP2);
    float* sRv  = reinterpret_cast<float*>(smemc + OFF_SRV);
    float* sBL  = reinterpret_cast<float*>(smemc + OFF_RED);
    int*   sBA  = reinterpret_cast<int*>(smemc + OFF_RED + 4);

    if (tid == 0) { *sBL = 0.0f; *sBA = 0; }

    // smem byte offsets (within a stage buffer)
    const uint32_t aoff = (uint32_t)(arow * (A_STR * 2) + acseg * 2);
    const uint32_t boff = (uint32_t)(brow * (A_STR * 2) + bcseg * 2);
    // ldmatrix address parts
    const uint32_t aP = (uint32_t)(((lane & 15) * A_STR + (lane >> 4) * 8) * 2);
    const uint32_t bP = (uint32_t)((((warp * 8) + (lane & 7)) * A_STR + ((lane >> 3) & 1) * 8) * 2);

    const float* xs[3]  = {xTF, xDE, xFFT};
    const float* ps[3]  = {pTF, pDE, pFFT};
    const float* vs[3]  = {vTF, vDE, vFFT};
    const float  wts[3] = {1.0f, 0.8f, 0.6f};

    float pred[8];
    #pragma unroll
    for (int i = 0; i < 8; i++) pred[i] = 0.0f;
    float lossAcc = 0.0f;
    const int lc = (tid & 7) * 8;          // softmax col stripe
    const int lr = tid >> 3;               // softmax row

    for (int m = 0; m < 3; m++) {
        if (tid < 64) sRv[tid] = 1.0f / vs[m][tid];

        const float* aptr = xs[m] + (rowbase + arow) * DIMK + acseg;
        const float* bptr = ps[m] + (size_t)brow * DIMK + bcseg;

        float x2acc = 0.0f, p2acc = 0.0f;
        float acc0[4] = {0,0,0,0}, acc1[4] = {0,0,0,0};

        // ---- fill chunk 0 into buf 0 ----
        {
            float4 a0 = *reinterpret_cast<const float4*>(aptr);
            float4 a1 = *reinterpret_cast<const float4*>(aptr + 4);
            float4 a2 = *reinterpret_cast<const float4*>(aptr + 8);
            float4 a3 = *reinterpret_cast<const float4*>(aptr + 12);
            uint4 hi, lo;
            split8(a0, a1, hi, lo);
            *reinterpret_cast<uint4*>(smemc + OFF_AH + aoff)      = hi;
            *reinterpret_cast<uint4*>(smemc + OFF_AL + aoff)      = lo;
            split8(a2, a3, hi, lo);
            *reinterpret_cast<uint4*>(smemc + OFF_AH + aoff + 16) = hi;
            *reinterpret_cast<uint4*>(smemc + OFF_AL + aoff + 16) = lo;
            x2acc += sq8(a0, a1) + sq8(a2, a3);

            #pragma unroll
            for (int q = 0; q < 4; q++) {
                float4 b0 = *reinterpret_cast<const float4*>(bptr + q * 8);
                float4 b1 = *reinterpret_cast<const float4*>(bptr + q * 8 + 4);
                split8(b0, b1, hi, lo);
                *reinterpret_cast<uint4*>(smemc + OFF_BH + boff + q * 16) = hi;
                *reinterpret_cast<uint4*>(smemc + OFF_BL + boff + q * 16) = lo;
                p2acc += sq8(b0, b1);
            }
        }
        __syncthreads();

        for (int ci = 0; ci < NCHUNK; ci++) {
            const uint32_t base = sb + (uint32_t)((ci & 1) * BUFSZ);
            const bool hasnext = (ci + 1 < NCHUNK);

            // prefetch next chunk into registers (issued before MMA block)
            float4 na0, na1, na2, na3, nb[8];
            if (hasnext) {
                const float* ap = aptr + (ci + 1) * KC;
                na0 = *reinterpret_cast<const float4*>(ap);
                na1 = *reinterpret_cast<const float4*>(ap + 4);
                na2 = *reinterpret_cast<const float4*>(ap + 8);
                na3 = *reinterpret_cast<const float4*>(ap + 12);
                const float* bp = bptr + (ci + 1) * KC;
                #pragma unroll
                for (int q = 0; q < 8; q++)
                    nb[q] = *reinterpret_cast<const float4*>(bp + q * 4);
            }

            // MMA on current buffer: 8 k-steps of 16 elems (32 bytes) each
            #pragma unroll
            for (int ks = 0; ks < 8; ks++) {
                uint32_t ah0[4], ah1[4], al0[4], al1[4], bhf[2], blf[2];
                const uint32_t ko = (uint32_t)(ks * 32);
                ldsm4(ah0, base + OFF_AH + aP + ko);
                ldsm4(ah1, base + OFF_AH + 4352 + aP + ko);
                ldsm4(al0, base + OFF_AL + aP + ko);
                ldsm4(al1, base + OFF_AL + 4352 + aP + ko);
                ldsm2(bhf, base + OFF_BH + bP + ko);
                ldsm2(blf, base + OFF_BL + bP + ko);
                mma_bf16(acc0, ah0, bhf);
                mma_bf16(acc0, ah0, blf);
                mma_bf16(acc0, al0, bhf);
                mma_bf16(acc1, ah1, bhf);
                mma_bf16(acc1, ah1, blf);
                mma_bf16(acc1, al1, bhf);
            }

            // split + store next chunk into other buffer
            if (hasnext) {
                const uint32_t nbase = (uint32_t)(((ci + 1) & 1) * BUFSZ);
                uint4 hi, lo;
                split8(na0, na1, hi, lo);
                *reinterpret_cast<uint4*>(smemc + nbase + OFF_AH + aoff)      = hi;
                *reinterpret_cast<uint4*>(smemc + nbase + OFF_AL + aoff)      = lo;
                split8(na2, na3, hi, lo);
                *reinterpret_cast<uint4*>(smemc + nbase + OFF_AH + aoff + 16) = hi;
                *reinterpret_cast<uint4*>(smemc + nbase + OFF_AL + aoff + 16) = lo;
                x2acc += sq8(na0, na1) + sq8(na2, na3);
                #pragma unroll
                for (int q = 0; q < 4; q++) {
                    split8(nb[2*q], nb[2*q+1], hi, lo);
                    *reinterpret_cast<uint4*>(smemc + nbase + OFF_BH + boff + q * 16) = hi;
                    *reinterpret_cast<uint4*>(smemc + nbase + OFF_BL + boff + q * 16) = lo;
                    p2acc += sq8(nb[2*q], nb[2*q+1]);
                }
            }
            __syncthreads();
        }

        // ---- reduce x2 (8 threads/row) and p2 (4 threads/proto) ----
        {
            float x2t = x2acc;
            x2t += __shfl_xor_sync(0xffffffffu, x2t, 1);
            x2t += __shfl_xor_sync(0xffffffffu, x2t, 2);
            x2t += __shfl_xor_sync(0xffffffffu, x2t, 4);
            if ((tid & 7) == 0) sX2[arow] = x2t;
            float p2t = p2acc;
            p2t += __shfl_xor_sync(0xffffffffu, p2t, 1);
            p2t += __shfl_xor_sync(0xffffffffu, p2t, 2);
            if ((tid & 3) == 0) sP2[brow] = p2t;
        }
        __syncthreads();

        // ---- logits into sL (reuses buf0) ----
        {
            const int c = warp * 8 + lk;
            const float p20 = sP2[c], p21 = sP2[c + 1];
            const float rv0 = sRv[c], rv1 = sRv[c + 1];
            #pragma unroll
            for (int mt = 0; mt < 2; mt++) {
                const float* A = mt ? acc1 : acc0;
                const int r0 = mt * 16 + gr;
                const float x2a = sX2[r0], x2b = sX2[r0 + 8];
                sL[r0 * SL_STR + c]           = fmaf(2.0f, A[0], -(x2a + p20)) * rv0;
                sL[r0 * SL_STR + c + 1]       = fmaf(2.0f, A[1], -(x2a + p21)) * rv1;
                sL[(r0 + 8) * SL_STR + c]     = fmaf(2.0f, A[2], -(x2b + p20)) * rv0;
                sL[(r0 + 8) * SL_STR + c + 1] = fmaf(2.0f, A[3], -(x2b + p21)) * rv1;
            }
        }
        __syncthreads();

        // ---- softmax per row (8 threads/row, 8-col stripes) ----
        {
            const float* Lr = sL + lr * SL_STR;
            float f[8];
            #pragma unroll
            for (int i = 0; i < 8; i++) f[i] = Lr[lc + i];
            const float Ly = Lr[cls];

            float mx = f[0];
            #pragma unroll
            for (int i = 1; i < 8; i++) mx = fmaxf(mx, f[i]);
            mx = fmaxf(mx, __shfl_xor_sync(0xffffffffu, mx, 1));
            mx = fmaxf(mx, __shfl_xor_sync(0xffffffffu, mx, 2));
            mx = fmaxf(mx, __shfl_xor_sync(0xffffffffu, mx, 4));

            float s = 0.0f;
            #pragma unroll
            for (int i = 0; i < 8; i++) { f[i] = __expf(f[i] - mx); s += f[i]; }
            s += __shfl_xor_sync(0xffffffffu, s, 1);
            s += __shfl_xor_sync(0xffffffffu, s, 2);
            s += __shfl_xor_sync(0xffffffffu, s, 4);

            const float winv = wts[m] / s;
            #pragma unroll
            for (int i = 0; i < 8; i++) pred[i] += f[i] * winv;

            if ((tid & 7) == (cls >> 3))
                lossAcc += -wts[m] * (Ly - mx - logf(s));
        }
        __syncthreads();
    }

    // ---- final: argmax over fused preds (first-max tie-break) + reduction ----
    {
        float bv = pred[0]; int bi = lc;
        #pragma unroll
        for (int i = 1; i < 8; i++)
            if (pred[i] > bv) { bv = pred[i]; bi = lc + i; }
        #pragma unroll
        for (int o = 1; o <= 4; o <<= 1) {
            const float ov = __shfl_xor_sync(0xffffffffu, bv, o);
            const int   oi = __shfl_xor_sync(0xffffffffu, bi, o);
            if (ov > bv || (ov == bv && oi < bi)) { bv = ov; bi = oi; }
        }
        float ls = lossAcc;
        ls += __shfl_xor_sync(0xffffffffu, ls, 1);
        ls += __shfl_xor_sync(0xffffffffu, ls, 2);
        ls += __shfl_xor_sync(0xffffffffu, ls, 4);

        float lrow = ((lane & 7) == 0) ? ls : 0.0f;
        int   arw  = ((lane & 7) == 0 && bi == cls) ? 1 : 0;
        lrow += __shfl_xor_sync(0xffffffffu, lrow, 8);
        lrow += __shfl_xor_sync(0xffffffffu, lrow, 16);
        arw  += __shfl_xor_sync(0xffffffffu, arw, 8);
        arw  += __shfl_xor_sync(0xffffffffu, arw, 16);
        if (lane == 0) {
            atomicAdd(sBL, lrow);
            atomicAdd(sBA, arw);
        }
    }
    __syncthreads();
    if (tid == 0)
        g_part[blockIdx.x] = make_float2(*sBL, (float)*sBA);
}

// ---------------------------------------------------------------------------
__global__ void finalize_kernel(float* __restrict__ out, int n)
{
    __shared__ float rl[8], ra[8];
    const int tid = threadIdx.x;
    float2 p = g_part[tid];
    float l = p.x, a = p.y;
    #pragma unroll
    for (int o = 16; o > 0; o >>= 1) {
        l += __shfl_xor_sync(0xffffffffu, l, o);
        a += __shfl_xor_sync(0xffffffffu, a, o);
    }
    if ((tid & 31) == 0) { rl[tid >> 5] = l; ra[tid >> 5] = a; }
    __syncthreads();
    if (tid == 0) {
        float ls = 0.0f, as = 0.0f;
        #pragma unroll
        for (int i = 0; i < 8; i++) { ls += rl[i]; as += ra[i]; }
        const float loss = ls * (1.0f / NROWS);
        const float acc  = as * (1.0f / NROWS);
        for (int i = 0; i < n; i++)
            out[i] = (i == 0) ? loss : (i == 1 ? acc : 0.0f);
    }
}

// ---------------------------------------------------------------------------
extern "C" void kernel_launch(void* const* d_in, const int* in_sizes, int n_in,
                              void* d_out, int out_size)
{
    (void)in_sizes; (void)n_in;
    const float* TFq  = (const float*)d_in[0];
    const float* pTF  = (const float*)d_in[1];
    const float* vTF  = (const float*)d_in[2];
    const float* DEq  = (const float*)d_in[3];
    const float* pDE  = (const float*)d_in[4];
    const float* vDE  = (const float*)d_in[5];
    const float* FFTq = (const float*)d_in[6];
    const float* pFFT = (const float*)d_in[7];
    const float* vFFT = (const float*)d_in[8];

    static int smem_set = 0;
    if (!smem_set) {
        cudaFuncSetAttribute(fusion_kernel, cudaFuncAttributeMaxDynamicSharedMemorySize, SMEM_TOTAL);
        smem_set = 1;
    }

    fusion_kernel<<<NCTA, 256, SMEM_TOTAL>>>(TFq, pTF, vTF, DEq, pDE, vDE, FFTq, pFFT, vFFT);
    finalize_kernel<<<1, 256>>>((float*)d_out, out_size);
}

// round 11
// speedup vs baseline: 1.7161x; 1.7161x over previous
#include <cuda_runtime.h>
#include <cuda_bf16.h>
#include <stdint.h>

#define KCLS   64
#define QPC    128
#define DIMK   1024
#define NROWS  (KCLS * QPC)      // 8192
#define TMR    32                // rows per CTA
#define NCTA   (NROWS / TMR)     // 256
#define KC     128               // k elems per chunk
#define NCHUNK (DIMK / KC)       // 8 per modality

// ---------------- smem layout (bytes), stride-136 bf16 rows (272B) ----------
#define A_STR   136
#define OFF_AH  0
#define OFF_AL  8704                     // 32*136*2
#define OFF_BH  17408
#define OFF_BL  34816                    // + 64*136*2
#define BUFSZ   52224
#define OFF_SL  0                        // logits reuse buf0 (32 x 72 fp32)
#define SL_STR  72
#define OFF_SX2 (2 * BUFSZ)              // 104448
#define OFF_SP2 (OFF_SX2 + 128)
#define OFF_SRV (OFF_SP2 + 256)
#define OFF_RED (OFF_SRV + 256)          // sBLoss (f32), sBAcc (int)
#define SMEM_TOTAL (OFF_RED + 64)        // 105152

__device__ float  g_p2[3][KCLS];
__device__ float  g_rvar[3][KCLS];
__device__ float2 g_part[NCTA];          // per-CTA (loss_sum, acc_count)
// pre-split protos: [m][chunk(8)][row(64)][16 uint4]  (row = 128 bf16 = 256 B)
__device__ uint4  g_Bh2[3 * NCHUNK * KCLS * 16];
__device__ uint4  g_Bl2[3 * NCHUNK * KCLS * 16];

// ---------------------------------------------------------------------------
__device__ __forceinline__ uint32_t smem_u32(const void* p) {
    uint32_t a;
    asm("{ .reg .u64 t; cvta.to.shared.u64 t, %1; cvt.u32.u64 %0, t; }" : "=r"(a) : "l"(p));
    return a;
}
__device__ __forceinline__ void cp16(uint32_t dst, const void* src) {
    asm volatile("cp.async.cg.shared.global [%0], [%1], 16;" :: "r"(dst), "l"(src) : "memory");
}
#define CP_COMMIT() asm volatile("cp.async.commit_group;" ::: "memory")
#define CP_WAIT0()  asm volatile("cp.async.wait_group 0;" ::: "memory")

__device__ __forceinline__ void ldsm4(uint32_t* r, uint32_t a) {
    asm volatile("ldmatrix.sync.aligned.m8n8.x4.shared.b16 {%0,%1,%2,%3}, [%4];"
                 : "=r"(r[0]), "=r"(r[1]), "=r"(r[2]), "=r"(r[3]) : "r"(a));
}
__device__ __forceinline__ void ldsm2(uint32_t* r, uint32_t a) {
    asm volatile("ldmatrix.sync.aligned.m8n8.x2.shared.b16 {%0,%1}, [%2];"
                 : "=r"(r[0]), "=r"(r[1]) : "r"(a));
}
__device__ __forceinline__ void mma_bf16(float c[4], const uint32_t a[4], const uint32_t b[2]) {
    asm volatile(
        "mma.sync.aligned.m16n8k16.row.col.f32.bf16.bf16.f32 "
        "{%0,%1,%2,%3}, {%4,%5,%6,%7}, {%8,%9}, {%0,%1,%2,%3};\n"
        : "+f"(c[0]), "+f"(c[1]), "+f"(c[2]), "+f"(c[3])
        : "r"(a[0]), "r"(a[1]), "r"(a[2]), "r"(a[3]), "r"(b[0]), "r"(b[1]));
}

// fp32x8 -> bf16 hi + bf16 lo
__device__ __forceinline__ void split8(float4 a, float4 b, uint4& hi, uint4& lo) {
    float f[8] = {a.x, a.y, a.z, a.w, b.x, b.y, b.z, b.w};
    uint32_t hw[4], lw[4];
    #pragma unroll
    for (int i = 0; i < 4; i++) {
        __nv_bfloat162 h = __floats2bfloat162_rn(f[2*i], f[2*i+1]);
        float r0 = f[2*i]     - __bfloat162float(h.x);
        float r1 = f[2*i + 1] - __bfloat162float(h.y);
        __nv_bfloat162 l = __floats2bfloat162_rn(r0, r1);
        hw[i] = *reinterpret_cast<uint32_t*>(&h);
        lw[i] = *reinterpret_cast<uint32_t*>(&l);
    }
    hi = make_uint4(hw[0], hw[1], hw[2], hw[3]);
    lo = make_uint4(lw[0], lw[1], lw[2], lw[3]);
}
__device__ __forceinline__ float sq8(float4 a, float4 b) {
    return a.x*a.x + a.y*a.y + a.z*a.z + a.w*a.w
         + b.x*b.x + b.y*b.y + b.z*b.z + b.w*b.w;
}

// ---------------------------------------------------------------------------
// prep: p2, 1/var, pre-split protos into chunk-major bf16 hi/lo
// grid 192 (m*64 + proto), 128 threads (8 cols each)
// ---------------------------------------------------------------------------
__global__ void prep_kernel(const float* __restrict__ pTF, const float* __restrict__ vTF,
                            const float* __restrict__ pDE, const float* __restrict__ vDE,
                            const float* __restrict__ pFFT, const float* __restrict__ vFFT)
{
    __shared__ float red[4];
    const int b = blockIdx.x;
    const int m = b >> 6, j = b & 63;
    const int tid = threadIdx.x;

    const float* P = (m == 0 ? pTF : (m == 1 ? pDE : pFFT)) + (size_t)j * DIMK;
    const int c0 = tid * 8;
    float4 x0 = *reinterpret_cast<const float4*>(P + c0);
    float4 x1 = *reinterpret_cast<const float4*>(P + c0 + 4);
    float s = sq8(x0, x1);

    uint4 hi, lo; split8(x0, x1, hi, lo);
    const int chunk = c0 >> 7;
    const int col   = c0 & 127;
    const size_t idx = (((size_t)(m * NCHUNK + chunk) * KCLS) + j) * 16 + (col >> 3);
    g_Bh2[idx] = hi;
    g_Bl2[idx] = lo;

    #pragma unroll
    for (int o = 16; o > 0; o >>= 1) s += __shfl_xor_sync(0xffffffffu, s, o);
    if ((tid & 31) == 0) red[tid >> 5] = s;
    __syncthreads();
    if (tid == 0) {
        g_p2[m][j] = red[0] + red[1] + red[2] + red[3];
        const float* V = (m == 0 ? vTF : (m == 1 ? vDE : vFFT));
        g_rvar[m][j] = 1.0f / V[j];
    }
}

// ---------------------------------------------------------------------------
// fused kernel: cp.async B + bf16 hi/lo-split HMMA GEMM + softmax/loss/argmax
// grid 256 CTAs x 256 threads; CTA = 32 rows of one class (cls = blockIdx.x>>2)
// ---------------------------------------------------------------------------
__global__ void __launch_bounds__(256, 2)
fusion_kernel(const float* __restrict__ xTF, const float* __restrict__ xDE,
              const float* __restrict__ xFFT)
{
    extern __shared__ unsigned char smemc[];
    const uint32_t sb = smem_u32(smemc);

    const int tid  = threadIdx.x;
    const int warp = tid >> 5;
    const int lane = tid & 31;
    const int gr   = lane >> 2;
    const int lk   = (lane & 3) * 2;
    const int cls  = (int)(blockIdx.x >> 2);
    const size_t rowbase = (size_t)blockIdx.x * TMR;

    // producer mappings (A)
    const int arow  = tid >> 3;            // 0..31
    const int acseg = (tid & 7) * 16;      // fp32 col base, 16 floats

    float* sL   = reinterpret_cast<float*>(smemc + OFF_SL);
    float* sX2  = reinterpret_cast<float*>(smemc + OFF_SX2);
    float* sP2  = reinterpret_cast<float*>(smemc + OFF_SP2);
    float* sRv  = reinterpret_cast<float*>(smemc + OFF_SRV);
    float* sBL  = reinterpret_cast<float*>(smemc + OFF_RED);
    int*   sBA  = reinterpret_cast<int*>(smemc + OFF_RED + 4);

    if (tid == 0) { *sBL = 0.0f; *sBA = 0; }

    const uint32_t aoff = (uint32_t)(arow * (A_STR * 2) + acseg * 2);
    // B cp.async dst offsets for this thread's 4 segments (s = tid + 256q)
    // dst byte (within B tile) = (s>>4)*272 + (s&15)*16
    // ldmatrix address parts
    const uint32_t aP = (uint32_t)(((lane & 15) * A_STR + (lane >> 4) * 8) * 2);
    const uint32_t bP = (uint32_t)((((warp * 8) + (lane & 7)) * A_STR + ((lane >> 3) & 1) * 8) * 2);

    const float* xs[3]  = {xTF, xDE, xFFT};
    const float  wts[3] = {1.0f, 0.8f, 0.6f};

    float pred[8];
    #pragma unroll
    for (int i = 0; i < 8; i++) pred[i] = 0.0f;
    float lossAcc = 0.0f;
    const int lc = (tid & 7) * 8;          // softmax col stripe
    const int lr = tid >> 3;               // softmax row

    for (int m = 0; m < 3; m++) {
        if (tid < 64) { sP2[tid] = g_p2[m][tid]; sRv[tid] = g_rvar[m][tid]; }

        const float* aptr = xs[m] + (rowbase + arow) * DIMK + acseg;
        const uint4* gH = g_Bh2 + (size_t)m * NCHUNK * (KCLS * 16);
        const uint4* gL = g_Bl2 + (size_t)m * NCHUNK * (KCLS * 16);

        float x2acc = 0.0f;
        float acc0[4] = {0,0,0,0}, acc1[4] = {0,0,0,0};

        // ---- preload chunk 0 into buf 0 ----
        {
            #pragma unroll
            for (int q = 0; q < 4; q++) {
                const int s = tid + 256 * q;
                const uint32_t d = (uint32_t)((s >> 4) * 272 + (s & 15) * 16);
                cp16(sb + OFF_BH + d, gH + s);
                cp16(sb + OFF_BL + d, gL + s);
            }
            CP_COMMIT();

            float4 a0 = *reinterpret_cast<const float4*>(aptr);
            float4 a1 = *reinterpret_cast<const float4*>(aptr + 4);
            float4 a2 = *reinterpret_cast<const float4*>(aptr + 8);
            float4 a3 = *reinterpret_cast<const float4*>(aptr + 12);
            x2acc += sq8(a0, a1) + sq8(a2, a3);
            uint4 hi, lo;
            split8(a0, a1, hi, lo);
            *reinterpret_cast<uint4*>(smemc + OFF_AH + aoff)      = hi;
            *reinterpret_cast<uint4*>(smemc + OFF_AL + aoff)      = lo;
            split8(a2, a3, hi, lo);
            *reinterpret_cast<uint4*>(smemc + OFF_AH + aoff + 16) = hi;
            *reinterpret_cast<uint4*>(smemc + OFF_AL + aoff + 16) = lo;

            CP_WAIT0();
            __syncthreads();
        }

        for (int ci = 0; ci < NCHUNK; ci++) {
            const uint32_t base = sb + (uint32_t)((ci & 1) * BUFSZ);
            const bool hasnext = (ci + 1 < NCHUNK);
            const uint32_t nbase = (uint32_t)(((ci + 1) & 1) * BUFSZ);

            // issue B copies for next chunk (no registers, overlaps MMA)
            float4 na0, na1, na2, na3;
            if (hasnext) {
                const uint4* nH = gH + (size_t)(ci + 1) * (KCLS * 16);
                const uint4* nL = gL + (size_t)(ci + 1) * (KCLS * 16);
                #pragma unroll
                for (int q = 0; q < 4; q++) {
                    const int s = tid + 256 * q;
                    const uint32_t d = nbase + (uint32_t)((s >> 4) * 272 + (s & 15) * 16);
                    cp16(sb + OFF_BH + d, nH + s);
                    cp16(sb + OFF_BL + d, nL + s);
                }
                CP_COMMIT();
                const float* ap = aptr + (ci + 1) * KC;
                na0 = *reinterpret_cast<const float4*>(ap);
                na1 = *reinterpret_cast<const float4*>(ap + 4);
                na2 = *reinterpret_cast<const float4*>(ap + 8);
                na3 = *reinterpret_cast<const float4*>(ap + 12);
            }

            // MMA on current buffer: 8 k-steps of 16 elems (32 bytes) each
            #pragma unroll
            for (int ks = 0; ks < 8; ks++) {
                uint32_t ah0[4], ah1[4], al0[4], al1[4], bhf[2], blf[2];
                const uint32_t ko = (uint32_t)(ks * 32);
                ldsm4(ah0, base + OFF_AH + aP + ko);
                ldsm4(ah1, base + OFF_AH + 4352 + aP + ko);
                ldsm4(al0, base + OFF_AL + aP + ko);
                ldsm4(al1, base + OFF_AL + 4352 + aP + ko);
                ldsm2(bhf, base + OFF_BH + bP + ko);
                ldsm2(blf, base + OFF_BL + bP + ko);
                mma_bf16(acc0, ah0, bhf);
                mma_bf16(acc0, ah0, blf);
                mma_bf16(acc0, al0, bhf);
                mma_bf16(acc1, ah1, bhf);
                mma_bf16(acc1, ah1, blf);
                mma_bf16(acc1, al1, bhf);
            }

            // convert + store next A into other buffer
            if (hasnext) {
                x2acc += sq8(na0, na1) + sq8(na2, na3);
                uint4 hi, lo;
                split8(na0, na1, hi, lo);
                *reinterpret_cast<uint4*>(smemc + nbase + OFF_AH + aoff)      = hi;
                *reinterpret_cast<uint4*>(smemc + nbase + OFF_AL + aoff)      = lo;
                split8(na2, na3, hi, lo);
                *reinterpret_cast<uint4*>(smemc + nbase + OFF_AH + aoff + 16) = hi;
                *reinterpret_cast<uint4*>(smemc + nbase + OFF_AL + aoff + 16) = lo;
            }

            CP_WAIT0();
            __syncthreads();
        }

        // ---- reduce x2 (8 threads/row) ----
        {
            float x2t = x2acc;
            x2t += __shfl_xor_sync(0xffffffffu, x2t, 1);
            x2t += __shfl_xor_sync(0xffffffffu, x2t, 2);
            x2t += __shfl_xor_sync(0xffffffffu, x2t, 4);
            if ((tid & 7) == 0) sX2[arow] = x2t;
        }
        __syncthreads();

        // ---- logits into sL (reuses buf0) ----
        {
            const int c = warp * 8 + lk;
            const float p20 = sP2[c], p21 = sP2[c + 1];
            const float rv0 = sRv[c], rv1 = sRv[c + 1];
            #pragma unroll
            for (int mt = 0; mt < 2; mt++) {
                const float* A = mt ? acc1 : acc0;
                const int r0 = mt * 16 + gr;
                const float x2a = sX2[r0], x2b = sX2[r0 + 8];
                sL[r0 * SL_STR + c]           = fmaf(2.0f, A[0], -(x2a + p20)) * rv0;
                sL[r0 * SL_STR + c + 1]       = fmaf(2.0f, A[1], -(x2a + p21)) * rv1;
                sL[(r0 + 8) * SL_STR + c]     = fmaf(2.0f, A[2], -(x2b + p20)) * rv0;
                sL[(r0 + 8) * SL_STR + c + 1] = fmaf(2.0f, A[3], -(x2b + p21)) * rv1;
            }
        }
        __syncthreads();

        // ---- softmax per row (8 threads/row, 8-col stripes) ----
        {
            const float* Lr = sL + lr * SL_STR;
            float f[8];
            #pragma unroll
            for (int i = 0; i < 8; i++) f[i] = Lr[lc + i];
            const float Ly = Lr[cls];

            float mx = f[0];
            #pragma unroll
            for (int i = 1; i < 8; i++) mx = fmaxf(mx, f[i]);
            mx = fmaxf(mx, __shfl_xor_sync(0xffffffffu, mx, 1));
            mx = fmaxf(mx, __shfl_xor_sync(0xffffffffu, mx, 2));
            mx = fmaxf(mx, __shfl_xor_sync(0xffffffffu, mx, 4));

            float s = 0.0f;
            #pragma unroll
            for (int i = 0; i < 8; i++) { f[i] = __expf(f[i] - mx); s += f[i]; }
            s += __shfl_xor_sync(0xffffffffu, s, 1);
            s += __shfl_xor_sync(0xffffffffu, s, 2);
            s += __shfl_xor_sync(0xffffffffu, s, 4);

            const float winv = wts[m] / s;
            #pragma unroll
            for (int i = 0; i < 8; i++) pred[i] += f[i] * winv;

            if ((tid & 7) == (cls >> 3))
                lossAcc += -wts[m] * (Ly - mx - logf(s));
        }
        __syncthreads();
    }

    // ---- final: argmax over fused preds (first-max tie-break) + reduction ----
    {
        float bv = pred[0]; int bi = lc;
        #pragma unroll
        for (int i = 1; i < 8; i++)
            if (pred[i] > bv) { bv = pred[i]; bi = lc + i; }
        #pragma unroll
        for (int o = 1; o <= 4; o <<= 1) {
            const float ov = __shfl_xor_sync(0xffffffffu, bv, o);
            const int   oi = __shfl_xor_sync(0xffffffffu, bi, o);
            if (ov > bv || (ov == bv && oi < bi)) { bv = ov; bi = oi; }
        }
        float ls = lossAcc;
        ls += __shfl_xor_sync(0xffffffffu, ls, 1);
        ls += __shfl_xor_sync(0xffffffffu, ls, 2);
        ls += __shfl_xor_sync(0xffffffffu, ls, 4);

        float lrow = ((lane & 7) == 0) ? ls : 0.0f;
        int   arw  = ((lane & 7) == 0 && bi == cls) ? 1 : 0;
        lrow += __shfl_xor_sync(0xffffffffu, lrow, 8);
        lrow += __shfl_xor_sync(0xffffffffu, lrow, 16);
        arw  += __shfl_xor_sync(0xffffffffu, arw, 8);
        arw  += __shfl_xor_sync(0xffffffffu, arw, 16);
        if (lane == 0) {
            atomicAdd(sBL, lrow);
            atomicAdd(sBA, arw);
        }
    }
    __syncthreads();
    if (tid == 0)
        g_part[blockIdx.x] = make_float2(*sBL, (float)*sBA);
}

// ---------------------------------------------------------------------------
__global__ void finalize_kernel(float* __restrict__ out, int n)
{
    __shared__ float rl[8], ra[8];
    const int tid = threadIdx.x;
    float2 p = g_part[tid];
    float l = p.x, a = p.y;
    #pragma unroll
    for (int o = 16; o > 0; o >>= 1) {
        l += __shfl_xor_sync(0xffffffffu, l, o);
        a += __shfl_xor_sync(0xffffffffu, a, o);
    }
    if ((tid & 31) == 0) { rl[tid >> 5] = l; ra[tid >> 5] = a; }
    __syncthreads();
    if (tid == 0) {
        float ls = 0.0f, as = 0.0f;
        #pragma unroll
        for (int i = 0; i < 8; i++) { ls += rl[i]; as += ra[i]; }
        const float loss = ls * (1.0f / NROWS);
        const float acc  = as * (1.0f / NROWS);
        for (int i = 0; i < n; i++)
            out[i] = (i == 0) ? loss : (i == 1 ? acc : 0.0f);
    }
}

// ---------------------------------------------------------------------------
extern "C" void kernel_launch(void* const* d_in, const int* in_sizes, int n_in,
                              void* d_out, int out_size)
{
    (void)in_sizes; (void)n_in;
    const float* TFq  = (const float*)d_in[0];
    const float* pTF  = (const float*)d_in[1];
    const float* vTF  = (const float*)d_in[2];
    const float* DEq  = (const float*)d_in[3];
    const float* pDE  = (const float*)d_in[4];
    const float* vDE  = (const float*)d_in[5];
    const float* FFTq = (const float*)d_in[6];
    const float* pFFT = (const float*)d_in[7];
    const float* vFFT = (const float*)d_in[8];

    static int smem_set = 0;
    if (!smem_set) {
        cudaFuncSetAttribute(fusion_kernel, cudaFuncAttributeMaxDynamicSharedMemorySize, SMEM_TOTAL);
        smem_set = 1;
    }

    prep_kernel<<<192, 128>>>(pTF, vTF, pDE, vDE, pFFT, vFFT);
    fusion_kernel<<<NCTA, 256, SMEM_TOTAL>>>(TFq, DEq, FFTq);
    finalize_kernel<<<1, 256>>>((float*)d_out, out_size);
}

// round 12
// speedup vs baseline: 1.9138x; 1.1152x over previous
#include <cuda_runtime.h>
#include <cuda_bf16.h>
#include <stdint.h>

#define KCLS   64
#define QPC    128
#define DIMK   1024
#define NROWS  (KCLS * QPC)      // 8192
#define TMR    32                // rows per CTA
#define NCTA   (NROWS / TMR)     // 256
#define KC     128               // k elems per chunk
#define NCHUNK (DIMK / KC)       // 8 per modality

// ---------------- smem layout (bytes), stride-136 bf16 rows (272B) ----------
#define A_STR   136
#define OFF_AH  0
#define OFF_AL  8704                     // 32*136*2
#define OFF_BH  17408
#define OFF_BL  34816                    // + 64*136*2
#define BUFSZ   52224
#define OFF_SL  0                        // logits reuse buf0 (32 x 72 fp32)
#define SL_STR  72
#define OFF_SX2 (2 * BUFSZ)              // 104448
#define OFF_SP2 (OFF_SX2 + 128)
#define OFF_SRV (OFF_SP2 + 256)
#define OFF_RED (OFF_SRV + 256)          // sBLoss (f32), sBAcc (int)
#define SMEM_TOTAL (OFF_RED + 64)        // 105152

__device__ float  g_p2[3][KCLS];
__device__ float  g_rvar[3][KCLS];
__device__ float2 g_part[NCTA];          // per-CTA (loss_sum, acc_count)
__device__ int    g_done;                // last-CTA counter (reset each run)
// pre-split protos: [m][chunk(8)][row(64)][16 uint4]  (row = 128 bf16 = 256 B)
__device__ uint4  g_Bh2[3 * NCHUNK * KCLS * 16];
__device__ uint4  g_Bl2[3 * NCHUNK * KCLS * 16];

// ---------------------------------------------------------------------------
__device__ __forceinline__ uint32_t smem_u32(const void* p) {
    uint32_t a;
    asm("{ .reg .u64 t; cvta.to.shared.u64 t, %1; cvt.u32.u64 %0, t; }" : "=r"(a) : "l"(p));
    return a;
}
__device__ __forceinline__ void cp16(uint32_t dst, const void* src) {
    asm volatile("cp.async.cg.shared.global [%0], [%1], 16;" :: "r"(dst), "l"(src) : "memory");
}
#define CP_COMMIT() asm volatile("cp.async.commit_group;" ::: "memory")
#define CP_WAIT0()  asm volatile("cp.async.wait_group 0;" ::: "memory")

__device__ __forceinline__ void ldsm4(uint32_t* r, uint32_t a) {
    asm volatile("ldmatrix.sync.aligned.m8n8.x4.shared.b16 {%0,%1,%2,%3}, [%4];"
                 : "=r"(r[0]), "=r"(r[1]), "=r"(r[2]), "=r"(r[3]) : "r"(a));
}
__device__ __forceinline__ void mma_bf16(float c[4], const uint32_t a[4], const uint32_t b[2]) {
    asm volatile(
        "mma.sync.aligned.m16n8k16.row.col.f32.bf16.bf16.f32 "
        "{%0,%1,%2,%3}, {%4,%5,%6,%7}, {%8,%9}, {%0,%1,%2,%3};\n"
        : "+f"(c[0]), "+f"(c[1]), "+f"(c[2]), "+f"(c[3])
        : "r"(a[0]), "r"(a[1]), "r"(a[2]), "r"(a[3]), "r"(b[0]), "r"(b[1]));
}

// fp32x8 -> bf16 hi + bf16 lo
__device__ __forceinline__ void split8(float4 a, float4 b, uint4& hi, uint4& lo) {
    float f[8] = {a.x, a.y, a.z, a.w, b.x, b.y, b.z, b.w};
    uint32_t hw[4], lw[4];
    #pragma unroll
    for (int i = 0; i < 4; i++) {
        __nv_bfloat162 h = __floats2bfloat162_rn(f[2*i], f[2*i+1]);
        float r0 = f[2*i]     - __bfloat162float(h.x);
        float r1 = f[2*i + 1] - __bfloat162float(h.y);
        __nv_bfloat162 l = __floats2bfloat162_rn(r0, r1);
        hw[i] = *reinterpret_cast<uint32_t*>(&h);
        lw[i] = *reinterpret_cast<uint32_t*>(&l);
    }
    hi = make_uint4(hw[0], hw[1], hw[2], hw[3]);
    lo = make_uint4(lw[0], lw[1], lw[2], lw[3]);
}
__device__ __forceinline__ float sq8(float4 a, float4 b) {
    return a.x*a.x + a.y*a.y + a.z*a.z + a.w*a.w
         + b.x*b.x + b.y*b.y + b.z*b.z + b.w*b.w;
}

// ---------------------------------------------------------------------------
// prep: p2, 1/var, pre-split protos into chunk-major bf16 hi/lo
// grid 192 (m*64 + proto), 128 threads (8 cols each)
// ---------------------------------------------------------------------------
__global__ void prep_kernel(const float* __restrict__ pTF, const float* __restrict__ vTF,
                            const float* __restrict__ pDE, const float* __restrict__ vDE,
                            const float* __restrict__ pFFT, const float* __restrict__ vFFT)
{
    __shared__ float red[4];
    const int b = blockIdx.x;
    const int m = b >> 6, j = b & 63;
    const int tid = threadIdx.x;

    const float* P = (m == 0 ? pTF : (m == 1 ? pDE : pFFT)) + (size_t)j * DIMK;
    const int c0 = tid * 8;
    float4 x0 = *reinterpret_cast<const float4*>(P + c0);
    float4 x1 = *reinterpret_cast<const float4*>(P + c0 + 4);
    float s = sq8(x0, x1);

    uint4 hi, lo; split8(x0, x1, hi, lo);
    const int chunk = c0 >> 7;
    const int col   = c0 & 127;
    const size_t idx = (((size_t)(m * NCHUNK + chunk) * KCLS) + j) * 16 + (col >> 3);
    g_Bh2[idx] = hi;
    g_Bl2[idx] = lo;

    #pragma unroll
    for (int o = 16; o > 0; o >>= 1) s += __shfl_xor_sync(0xffffffffu, s, o);
    if ((tid & 31) == 0) red[tid >> 5] = s;
    __syncthreads();
    if (tid == 0) {
        g_p2[m][j] = red[0] + red[1] + red[2] + red[3];
        const float* V = (m == 0 ? vTF : (m == 1 ? vDE : vFFT));
        g_rvar[m][j] = 1.0f / V[j];
    }
}

// ---------------------------------------------------------------------------
// fused kernel: cp.async B + bf16 hi/lo-split HMMA (m16n16 warp tiles) +
// softmax/loss/argmax + last-CTA final reduction.
// grid 256 CTAs x 256 threads; CTA = 32 rows of one class (cls = blockIdx.x>>2)
// ---------------------------------------------------------------------------
__global__ void __launch_bounds__(256, 2)
fusion_kernel(const float* __restrict__ xTF, const float* __restrict__ xDE,
              const float* __restrict__ xFFT, float* __restrict__ out, int out_size)
{
    extern __shared__ unsigned char smemc[];
    __shared__ int sLast;
    const uint32_t sb = smem_u32(smemc);

    const int tid  = threadIdx.x;
    const int warp = tid >> 5;
    const int lane = tid & 31;
    const int wm   = warp >> 2;            // 0..1  (A row block of 16)
    const int wn   = warp & 3;             // 0..3  (B col block of 16)
    const int gr   = lane >> 2;
    const int lk   = (lane & 3) * 2;
    const int cls  = (int)(blockIdx.x >> 2);
    const size_t rowbase = (size_t)blockIdx.x * TMR;

    // producer mappings (A)
    const int arow  = tid >> 3;            // 0..31
    const int acseg = (tid & 7) * 16;      // fp32 col base, 16 floats

    float* sL   = reinterpret_cast<float*>(smemc + OFF_SL);
    float* sX2  = reinterpret_cast<float*>(smemc + OFF_SX2);
    float* sP2  = reinterpret_cast<float*>(smemc + OFF_SP2);
    float* sRv  = reinterpret_cast<float*>(smemc + OFF_SRV);
    float* sBL  = reinterpret_cast<float*>(smemc + OFF_RED);
    int*   sBA  = reinterpret_cast<int*>(smemc + OFF_RED + 4);

    if (tid == 0) { *sBL = 0.0f; *sBA = 0; }

    const uint32_t aoff = (uint32_t)(arow * (A_STR * 2) + acseg * 2);
    // ldmatrix address parts:
    // A (m16k16): rows wm*16 + (lane&15), k-half (lane>>4)*8
    const uint32_t aPm = (uint32_t)(((wm * 16 + (lane & 15)) * A_STR + (lane >> 4) * 8) * 2);
    // B (n16k16): group = lane>>3 -> (n-half = group>>1, k-half = group&1)
    const uint32_t bPn = (uint32_t)(((wn * 16 + ((lane >> 3) >> 1) * 8 + (lane & 7)) * A_STR
                                     + ((lane >> 3) & 1) * 8) * 2);

    const float* xs[3]  = {xTF, xDE, xFFT};
    const float  wts[3] = {1.0f, 0.8f, 0.6f};

    float pred[8];
    #pragma unroll
    for (int i = 0; i < 8; i++) pred[i] = 0.0f;
    float lossAcc = 0.0f;
    const int lc = (tid & 7) * 8;          // softmax col stripe
    const int lr = tid >> 3;               // softmax row

    for (int m = 0; m < 3; m++) {
        if (tid < 64) { sP2[tid] = g_p2[m][tid]; sRv[tid] = g_rvar[m][tid]; }

        const float* aptr = xs[m] + (rowbase + arow) * DIMK + acseg;
        const uint4* gH = g_Bh2 + (size_t)m * NCHUNK * (KCLS * 16);
        const uint4* gL = g_Bl2 + (size_t)m * NCHUNK * (KCLS * 16);

        float x2acc = 0.0f;
        float acc[2][4] = {{0,0,0,0},{0,0,0,0}};

        // ---- preload chunk 0 into buf 0 ----
        {
            #pragma unroll
            for (int q = 0; q < 4; q++) {
                const int s = tid + 256 * q;
                const uint32_t d = (uint32_t)((s >> 4) * 272 + (s & 15) * 16);
                cp16(sb + OFF_BH + d, gH + s);
                cp16(sb + OFF_BL + d, gL + s);
            }
            CP_COMMIT();

            float4 a0 = *reinterpret_cast<const float4*>(aptr);
            float4 a1 = *reinterpret_cast<const float4*>(aptr + 4);
            float4 a2 = *reinterpret_cast<const float4*>(aptr + 8);
            float4 a3 = *reinterpret_cast<const float4*>(aptr + 12);
            x2acc += sq8(a0, a1) + sq8(a2, a3);
            uint4 hi, lo;
            split8(a0, a1, hi, lo);
            *reinterpret_cast<uint4*>(smemc + OFF_AH + aoff)      = hi;
            *reinterpret_cast<uint4*>(smemc + OFF_AL + aoff)      = lo;
            split8(a2, a3, hi, lo);
            *reinterpret_cast<uint4*>(smemc + OFF_AH + aoff + 16) = hi;
            *reinterpret_cast<uint4*>(smemc + OFF_AL + aoff + 16) = lo;

            CP_WAIT0();
            __syncthreads();
        }

        for (int ci = 0; ci < NCHUNK; ci++) {
            const uint32_t base = sb + (uint32_t)((ci & 1) * BUFSZ);
            const bool hasnext = (ci + 1 < NCHUNK);
            const uint32_t nbase = (uint32_t)(((ci + 1) & 1) * BUFSZ);

            // issue B copies for next chunk (no registers, overlaps MMA)
            float4 na0, na1, na2, na3;
            if (hasnext) {
                const uint4* nH = gH + (size_t)(ci + 1) * (KCLS * 16);
                const uint4* nL = gL + (size_t)(ci + 1) * (KCLS * 16);
                #pragma unroll
                for (int q = 0; q < 4; q++) {
                    const int s = tid + 256 * q;
                    const uint32_t d = nbase + (uint32_t)((s >> 4) * 272 + (s & 15) * 16);
                    cp16(sb + OFF_BH + d, nH + s);
                    cp16(sb + OFF_BL + d, nL + s);
                }
                CP_COMMIT();
                const float* ap = aptr + (ci + 1) * KC;
                na0 = *reinterpret_cast<const float4*>(ap);
                na1 = *reinterpret_cast<const float4*>(ap + 4);
                na2 = *reinterpret_cast<const float4*>(ap + 8);
                na3 = *reinterpret_cast<const float4*>(ap + 12);
            }

            // MMA on current buffer: 8 k-steps x (4 ldsm4 + 6 HMMA)
            #pragma unroll
            for (int ks = 0; ks < 8; ks++) {
                uint32_t ah[4], al[4], bh[4], bl[4];
                const uint32_t ko = (uint32_t)(ks * 32);
                ldsm4(ah, base + OFF_AH + aPm + ko);
                ldsm4(al, base + OFF_AL + aPm + ko);
                ldsm4(bh, base + OFF_BH + bPn + ko);
                ldsm4(bl, base + OFF_BL + bPn + ko);
                mma_bf16(acc[0], ah, bh);
                mma_bf16(acc[0], ah, bl);
                mma_bf16(acc[0], al, bh);
                mma_bf16(acc[1], ah, bh + 2);
                mma_bf16(acc[1], ah, bl + 2);
                mma_bf16(acc[1], al, bh + 2);
            }

            // convert + store next A into other buffer
            if (hasnext) {
                x2acc += sq8(na0, na1) + sq8(na2, na3);
                uint4 hi, lo;
                split8(na0, na1, hi, lo);
                *reinterpret_cast<uint4*>(smemc + nbase + OFF_AH + aoff)      = hi;
                *reinterpret_cast<uint4*>(smemc + nbase + OFF_AL + aoff)      = lo;
                split8(na2, na3, hi, lo);
                *reinterpret_cast<uint4*>(smemc + nbase + OFF_AH + aoff + 16) = hi;
                *reinterpret_cast<uint4*>(smemc + nbase + OFF_AL + aoff + 16) = lo;
            }

            CP_WAIT0();
            __syncthreads();
        }

        // ---- reduce x2 (8 threads/row) ----
        {
            float x2t = x2acc;
            x2t += __shfl_xor_sync(0xffffffffu, x2t, 1);
            x2t += __shfl_xor_sync(0xffffffffu, x2t, 2);
            x2t += __shfl_xor_sync(0xffffffffu, x2t, 4);
            if ((tid & 7) == 0) sX2[arow] = x2t;
        }
        __syncthreads();

        // ---- logits into sL (reuses buf0); warp covers rows wm*16.., cols wn*16.. ----
        {
            #pragma unroll
            for (int nt = 0; nt < 2; nt++) {
                const int c = wn * 16 + nt * 8 + lk;
                const float p20 = sP2[c], p21 = sP2[c + 1];
                const float rv0 = sRv[c], rv1 = sRv[c + 1];
                const int r0 = wm * 16 + gr;
                const float x2a = sX2[r0], x2b = sX2[r0 + 8];
                const float* A = acc[nt];
                sL[r0 * SL_STR + c]           = fmaf(2.0f, A[0], -(x2a + p20)) * rv0;
                sL[r0 * SL_STR + c + 1]       = fmaf(2.0f, A[1], -(x2a + p21)) * rv1;
                sL[(r0 + 8) * SL_STR + c]     = fmaf(2.0f, A[2], -(x2b + p20)) * rv0;
                sL[(r0 + 8) * SL_STR + c + 1] = fmaf(2.0f, A[3], -(x2b + p21)) * rv1;
            }
        }
        __syncthreads();

        // ---- softmax per row (8 threads/row, 8-col stripes) ----
        {
            const float* Lr = sL + lr * SL_STR;
            float f[8];
            #pragma unroll
            for (int i = 0; i < 8; i++) f[i] = Lr[lc + i];
            const float Ly = Lr[cls];

            float mx = f[0];
            #pragma unroll
            for (int i = 1; i < 8; i++) mx = fmaxf(mx, f[i]);
            mx = fmaxf(mx, __shfl_xor_sync(0xffffffffu, mx, 1));
            mx = fmaxf(mx, __shfl_xor_sync(0xffffffffu, mx, 2));
            mx = fmaxf(mx, __shfl_xor_sync(0xffffffffu, mx, 4));

            float s = 0.0f;
            #pragma unroll
            for (int i = 0; i < 8; i++) { f[i] = __expf(f[i] - mx); s += f[i]; }
            s += __shfl_xor_sync(0xffffffffu, s, 1);
            s += __shfl_xor_sync(0xffffffffu, s, 2);
            s += __shfl_xor_sync(0xffffffffu, s, 4);

            const float winv = wts[m] / s;
            #pragma unroll
            for (int i = 0; i < 8; i++) pred[i] += f[i] * winv;

            if ((tid & 7) == (cls >> 3))
                lossAcc += -wts[m] * (Ly - mx - logf(s));
        }
        __syncthreads();
    }

    // ---- final: argmax over fused preds (first-max tie-break) + reduction ----
    {
        float bv = pred[0]; int bi = lc;
        #pragma unroll
        for (int i = 1; i < 8; i++)
            if (pred[i] > bv) { bv = pred[i]; bi = lc + i; }
        #pragma unroll
        for (int o = 1; o <= 4; o <<= 1) {
            const float ov = __shfl_xor_sync(0xffffffffu, bv, o);
            const int   oi = __shfl_xor_sync(0xffffffffu, bi, o);
            if (ov > bv || (ov == bv && oi < bi)) { bv = ov; bi = oi; }
        }
        float ls = lossAcc;
        ls += __shfl_xor_sync(0xffffffffu, ls, 1);
        ls += __shfl_xor_sync(0xffffffffu, ls, 2);
        ls += __shfl_xor_sync(0xffffffffu, ls, 4);

        float lrow = ((lane & 7) == 0) ? ls : 0.0f;
        int   arw  = ((lane & 7) == 0 && bi == cls) ? 1 : 0;
        lrow += __shfl_xor_sync(0xffffffffu, lrow, 8);
        lrow += __shfl_xor_sync(0xffffffffu, lrow, 16);
        arw  += __shfl_xor_sync(0xffffffffu, arw, 8);
        arw  += __shfl_xor_sync(0xffffffffu, arw, 16);
        if (lane == 0) {
            atomicAdd(sBL, lrow);
            atomicAdd(sBA, arw);
        }
    }
    __syncthreads();
    if (tid == 0) {
        g_part[blockIdx.x] = make_float2(*sBL, (float)*sBA);
        __threadfence();
        const int v = atomicAdd(&g_done, 1);
        sLast = (v == NCTA - 1) ? 1 : 0;
    }
    __syncthreads();

    // ---- last CTA: reduce all partials, write output, reset counter ----
    if (sLast) {
        float2 p = g_part[tid];
        float l = p.x, a = p.y;
        #pragma unroll
        for (int o = 16; o > 0; o >>= 1) {
            l += __shfl_xor_sync(0xffffffffu, l, o);
            a += __shfl_xor_sync(0xffffffffu, a, o);
        }
        float* rl = sX2;        // reuse smem scratch
        float* ra = sX2 + 8;
        if ((tid & 31) == 0) { rl[warp] = l; ra[warp] = a; }
        __syncthreads();
        if (tid == 0) {
            float ls = 0.0f, as = 0.0f;
            #pragma unroll
            for (int i = 0; i < 8; i++) { ls += rl[i]; as += ra[i]; }
            out[0] = ls * (1.0f / NROWS);
            if (out_size > 1) out[1] = as * (1.0f / NROWS);
            for (int i = 2; i < out_size; i++) out[i] = 0.0f;
            g_done = 0;          // reset for next graph replay
        }
    }
}

// ---------------------------------------------------------------------------
extern "C" void kernel_launch(void* const* d_in, const int* in_sizes, int n_in,
                              void* d_out, int out_size)
{
    (void)in_sizes; (void)n_in;
    const float* TFq  = (const float*)d_in[0];
    const float* pTF  = (const float*)d_in[1];
    const float* vTF  = (const float*)d_in[2];
    const float* DEq  = (const float*)d_in[3];
    const float* pDE  = (const float*)d_in[4];
    const float* vDE  = (const float*)d_in[5];
    const float* FFTq = (const float*)d_in[6];
    const float* pFFT = (const float*)d_in[7];
    const float* vFFT = (const float*)d_in[8];

    static int smem_set = 0;
    if (!smem_set) {
        cudaFuncSetAttribute(fusion_kernel, cudaFuncAttributeMaxDynamicSharedMemorySize, SMEM_TOTAL);
        smem_set = 1;
    }

    prep_kernel<<<192, 128>>>(pTF, vTF, pDE, vDE, pFFT, vFFT);
    fusion_kernel<<<NCTA, 256, SMEM_TOTAL>>>(TFq, DEq, FFTq, (float*)d_out, out_size);
}

// round 13
// speedup vs baseline: 2.2708x; 1.1865x over previous
#include <cuda_runtime.h>
#include <cuda_bf16.h>
#include <stdint.h>

#define KCLS   64
#define QPC    128
#define DIMK   1024
#define NROWS  (KCLS * QPC)      // 8192
#define TMR    32                // rows per CTA
#define NCTA   (NROWS / TMR)     // 256
#define KC     64                // k elems per chunk
#define NCHUNK (DIMK / KC)       // 16 per modality

// ---------------- smem layout (bytes), stride-72 bf16 rows (144B) -----------
#define A_STR   72
#define OFF_AH  0
#define OFF_AL  4608                     // 32*144
#define OFF_BH  9216
#define OFF_BL  18432                    // + 64*144
#define BUFSZ   27648
#define NSTAGE  3
#define OFF_SL  0                        // logits reuse stage0 A region (9216B)
#define SL_STR  72
#define OFF_SX2 (NSTAGE * BUFSZ)         // 82944
#define OFF_SP2 (OFF_SX2 + 128)
#define OFF_SRV (OFF_SP2 + 256)
#define OFF_RED (OFF_SRV + 256)
#define SMEM_TOTAL (OFF_RED + 64)        // 83648 -> 2 CTAs/SM

__device__ float  g_p2[3][KCLS];
__device__ float  g_rvar[3][KCLS];
__device__ float2 g_part[NCTA];
__device__ int    g_done;
// pre-split protos: [m][chunk(16)][row(64)][8 uint4]  (row = 64 bf16 = 128 B)
__device__ uint4  g_Bh2[3 * NCHUNK * KCLS * 8];
__device__ uint4  g_Bl2[3 * NCHUNK * KCLS * 8];

// ---------------------------------------------------------------------------
__device__ __forceinline__ uint32_t smem_u32(const void* p) {
    uint32_t a;
    asm("{ .reg .u64 t; cvta.to.shared.u64 t, %1; cvt.u32.u64 %0, t; }" : "=r"(a) : "l"(p));
    return a;
}
__device__ __forceinline__ void cp16(uint32_t dst, const void* src) {
    asm volatile("cp.async.cg.shared.global [%0], [%1], 16;" :: "r"(dst), "l"(src) : "memory");
}
#define CP_COMMIT() asm volatile("cp.async.commit_group;" ::: "memory")
#define CP_WAIT0()  asm volatile("cp.async.wait_group 0;" ::: "memory")
#define CP_WAIT1()  asm volatile("cp.async.wait_group 1;" ::: "memory")

__device__ __forceinline__ void ldsm4(uint32_t* r, uint32_t a) {
    asm volatile("ldmatrix.sync.aligned.m8n8.x4.shared.b16 {%0,%1,%2,%3}, [%4];"
                 : "=r"(r[0]), "=r"(r[1]), "=r"(r[2]), "=r"(r[3]) : "r"(a));
}
__device__ __forceinline__ void mma_bf16(float c[4], const uint32_t a[4], const uint32_t b[2]) {
    asm volatile(
        "mma.sync.aligned.m16n8k16.row.col.f32.bf16.bf16.f32 "
        "{%0,%1,%2,%3}, {%4,%5,%6,%7}, {%8,%9}, {%0,%1,%2,%3};\n"
        : "+f"(c[0]), "+f"(c[1]), "+f"(c[2]), "+f"(c[3])
        : "r"(a[0]), "r"(a[1]), "r"(a[2]), "r"(a[3]), "r"(b[0]), "r"(b[1]));
}

// fp32x8 -> bf16 hi + bf16 lo
__device__ __forceinline__ void split8(float4 a, float4 b, uint4& hi, uint4& lo) {
    float f[8] = {a.x, a.y, a.z, a.w, b.x, b.y, b.z, b.w};
    uint32_t hw[4], lw[4];
    #pragma unroll
    for (int i = 0; i < 4; i++) {
        __nv_bfloat162 h = __floats2bfloat162_rn(f[2*i], f[2*i+1]);
        float r0 = f[2*i]     - __bfloat162float(h.x);
        float r1 = f[2*i + 1] - __bfloat162float(h.y);
        __nv_bfloat162 l = __floats2bfloat162_rn(r0, r1);
        hw[i] = *reinterpret_cast<uint32_t*>(&h);
        lw[i] = *reinterpret_cast<uint32_t*>(&l);
    }
    hi = make_uint4(hw[0], hw[1], hw[2], hw[3]);
    lo = make_uint4(lw[0], lw[1], lw[2], lw[3]);
}
__device__ __forceinline__ float sq8(float4 a, float4 b) {
    return a.x*a.x + a.y*a.y + a.z*a.z + a.w*a.w
         + b.x*b.x + b.y*b.y + b.z*b.z + b.w*b.w;
}

// ---------------------------------------------------------------------------
// prep: p2, 1/var, pre-split protos into chunk-major bf16 hi/lo (KC=64 rows)
// ---------------------------------------------------------------------------
__global__ void prep_kernel(const float* __restrict__ pTF, const float* __restrict__ vTF,
                            const float* __restrict__ pDE, const float* __restrict__ vDE,
                            const float* __restrict__ pFFT, const float* __restrict__ vFFT)
{
    __shared__ float red[4];
    const int b = blockIdx.x;
    const int m = b >> 6, j = b & 63;
    const int tid = threadIdx.x;

    const float* P = (m == 0 ? pTF : (m == 1 ? pDE : pFFT)) + (size_t)j * DIMK;
    const int c0 = tid * 8;
    float4 x0 = *reinterpret_cast<const float4*>(P + c0);
    float4 x1 = *reinterpret_cast<const float4*>(P + c0 + 4);
    float s = sq8(x0, x1);

    uint4 hi, lo; split8(x0, x1, hi, lo);
    const int chunk = c0 >> 6;
    const int col   = c0 & 63;
    const size_t idx = (((size_t)(m * NCHUNK + chunk) * KCLS) + j) * 8 + (col >> 3);
    g_Bh2[idx] = hi;
    g_Bl2[idx] = lo;

    #pragma unroll
    for (int o = 16; o > 0; o >>= 1) s += __shfl_xor_sync(0xffffffffu, s, o);
    if ((tid & 31) == 0) red[tid >> 5] = s;
    __syncthreads();
    if (tid == 0) {
        g_p2[m][j] = red[0] + red[1] + red[2] + red[3];
        const float* V = (m == 0 ? vTF : (m == 1 ? vDE : vFFT));
        g_rvar[m][j] = 1.0f / V[j];
    }
}

// ---------------------------------------------------------------------------
// fused kernel: 3-stage cp.async B ring + ks-pipelined bf16 hi/lo HMMA +
// softmax/loss/argmax + last-CTA reduction. 256 CTAs x 256 threads.
// ---------------------------------------------------------------------------
__global__ void __launch_bounds__(256, 2)
fusion_kernel(const float* __restrict__ xTF, const float* __restrict__ xDE,
              const float* __restrict__ xFFT, float* __restrict__ out, int out_size)
{
    extern __shared__ unsigned char smemc[];
    __shared__ int sLast;
    const uint32_t sb = smem_u32(smemc);

    const int tid  = threadIdx.x;
    const int warp = tid >> 5;
    const int lane = tid & 31;
    const int wm   = warp >> 2;            // 0..1  A row block (16)
    const int wn   = warp & 3;             // 0..3  B col block (16)
    const int gr   = lane >> 2;
    const int lk   = (lane & 3) * 2;
    const int cls  = (int)(blockIdx.x >> 2);
    const size_t rowbase = (size_t)blockIdx.x * TMR;

    // producer mappings (A): 8 threads/row, 8 floats each
    const int arow  = tid >> 3;
    const int acseg = (tid & 7) * 8;

    float* sL   = reinterpret_cast<float*>(smemc + OFF_SL);
    float* sX2  = reinterpret_cast<float*>(smemc + OFF_SX2);
    float* sP2  = reinterpret_cast<float*>(smemc + OFF_SP2);
    float* sRv  = reinterpret_cast<float*>(smemc + OFF_SRV);
    float* sBL  = reinterpret_cast<float*>(smemc + OFF_RED);
    int*   sBA  = reinterpret_cast<int*>(smemc + OFF_RED + 4);

    if (tid == 0) { *sBL = 0.0f; *sBA = 0; }

    const uint32_t aoff = (uint32_t)(arow * 144 + acseg * 2);
    // B cp.async dst (per thread, 2 segs): s = tid + 256q -> row s>>3, 16B col s&7
    // ldmatrix address parts
    const uint32_t aPm = (uint32_t)(((wm * 16 + (lane & 15)) * A_STR + (lane >> 4) * 8) * 2);
    const uint32_t bPn = (uint32_t)(((wn * 16 + ((lane >> 3) >> 1) * 8 + (lane & 7)) * A_STR
                                     + ((lane >> 3) & 1) * 8) * 2);

    const float* xs[3]  = {xTF, xDE, xFFT};
    const float  wts[3] = {1.0f, 0.8f, 0.6f};

    float pred[8];
    #pragma unroll
    for (int i = 0; i < 8; i++) pred[i] = 0.0f;
    float lossAcc = 0.0f;
    const int lc = (tid & 7) * 8;
    const int lr = tid >> 3;

    for (int m = 0; m < 3; m++) {
        if (tid < 64) { sP2[tid] = g_p2[m][tid]; sRv[tid] = g_rvar[m][tid]; }

        const float* aptr = xs[m] + (rowbase + arow) * DIMK + acseg;
        const uint4* gH = g_Bh2 + (size_t)m * NCHUNK * (KCLS * 8);
        const uint4* gL = g_Bl2 + (size_t)m * NCHUNK * (KCLS * 8);

        float x2acc = 0.0f;
        float acc[2][4] = {{0,0,0,0},{0,0,0,0}};

        // ---- prologue: B[0]->stage0, B[1]->stage1 (2 groups), A[0]->stage0 ----
        {
            #pragma unroll
            for (int q = 0; q < 2; q++) {
                const int s = tid + 256 * q;
                const uint32_t d = (uint32_t)((s >> 3) * 144 + (s & 7) * 16);
                cp16(sb + OFF_BH + d, gH + s);
                cp16(sb + OFF_BL + d, gL + s);
            }
            CP_COMMIT();
            #pragma unroll
            for (int q = 0; q < 2; q++) {
                const int s = tid + 256 * q;
                const uint32_t d = (uint32_t)(BUFSZ + (s >> 3) * 144 + (s & 7) * 16);
                cp16(sb + OFF_BH + d, gH + (KCLS * 8) + s);
                cp16(sb + OFF_BL + d, gL + (KCLS * 8) + s);
            }
            CP_COMMIT();

            float4 a0 = *reinterpret_cast<const float4*>(aptr);
            float4 a1 = *reinterpret_cast<const float4*>(aptr + 4);
            x2acc += sq8(a0, a1);
            uint4 hi, lo;
            split8(a0, a1, hi, lo);
            *reinterpret_cast<uint4*>(smemc + OFF_AH + aoff) = hi;
            *reinterpret_cast<uint4*>(smemc + OFF_AL + aoff) = lo;

            CP_WAIT1();          // B[0] landed; B[1] still in flight
            __syncthreads();
        }

        for (int ci = 0; ci < NCHUNK; ci++) {
            const int st  = ci % NSTAGE;
            const uint32_t base = sb + (uint32_t)(st * BUFSZ);
            const bool hn1 = (ci + 1 < NCHUNK);
            const bool hn2 = (ci + 2 < NCHUNK);

            // 1. issue B copies for ci+2 into stage (ci+2)%3
            if (hn2) {
                const int st2 = (ci + 2) % NSTAGE;
                const uint4* nH = gH + (size_t)(ci + 2) * (KCLS * 8);
                const uint4* nL = gL + (size_t)(ci + 2) * (KCLS * 8);
                #pragma unroll
                for (int q = 0; q < 2; q++) {
                    const int s = tid + 256 * q;
                    const uint32_t d = (uint32_t)(st2 * BUFSZ + (s >> 3) * 144 + (s & 7) * 16);
                    cp16(sb + OFF_BH + d, nH + s);
                    cp16(sb + OFF_BL + d, nL + s);
                }
                CP_COMMIT();
            }

            // 2. A prefetch for ci+1 (LDG into regs)
            float4 na0, na1;
            if (hn1) {
                const float* ap = aptr + (ci + 1) * KC;
                na0 = *reinterpret_cast<const float4*>(ap);
                na1 = *reinterpret_cast<const float4*>(ap + 4);
            }

            // 3. MMA on stage ci%3, fragments software-pipelined over 4 k-steps
            {
                uint32_t fr[2][16];
                ldsm4(fr[0],      base + OFF_AH + aPm);
                ldsm4(fr[0] + 4,  base + OFF_AL + aPm);
                ldsm4(fr[0] + 8,  base + OFF_BH + bPn);
                ldsm4(fr[0] + 12, base + OFF_BL + bPn);
                #pragma unroll
                for (int ks = 0; ks < 4; ks++) {
                    const int cur = ks & 1, nxt = cur ^ 1;
                    if (ks < 3) {
                        const uint32_t ko = (uint32_t)((ks + 1) * 32);
                        ldsm4(fr[nxt],      base + OFF_AH + aPm + ko);
                        ldsm4(fr[nxt] + 4,  base + OFF_AL + aPm + ko);
                        ldsm4(fr[nxt] + 8,  base + OFF_BH + bPn + ko);
                        ldsm4(fr[nxt] + 12, base + OFF_BL + bPn + ko);
                    }
                    const uint32_t* ah = fr[cur];
                    const uint32_t* al = fr[cur] + 4;
                    const uint32_t* bh = fr[cur] + 8;
                    const uint32_t* bl = fr[cur] + 12;
                    mma_bf16(acc[0], ah, bh);
                    mma_bf16(acc[1], ah, bh + 2);
                    mma_bf16(acc[0], ah, bl);
                    mma_bf16(acc[1], ah, bl + 2);
                    mma_bf16(acc[0], al, bh);
                    mma_bf16(acc[1], al, bh + 2);
                }
            }

            // 4. convert + store A[ci+1] into stage (ci+1)%3
            if (hn1) {
                const uint32_t nb = (uint32_t)(((ci + 1) % NSTAGE) * BUFSZ);
                x2acc += sq8(na0, na1);
                uint4 hi, lo;
                split8(na0, na1, hi, lo);
                *reinterpret_cast<uint4*>(smemc + nb + OFF_AH + aoff) = hi;
                *reinterpret_cast<uint4*>(smemc + nb + OFF_AL + aoff) = lo;
            }

            // 5. ensure B[ci+1] landed (keep at most the newest group pending)
            if (hn2) CP_WAIT1(); else CP_WAIT0();
            // 6. publish
            __syncthreads();
        }

        // ---- reduce x2 (8 threads/row) ----
        {
            float x2t = x2acc;
            x2t += __shfl_xor_sync(0xffffffffu, x2t, 1);
            x2t += __shfl_xor_sync(0xffffffffu, x2t, 2);
            x2t += __shfl_xor_sync(0xffffffffu, x2t, 4);
            if ((tid & 7) == 0) sX2[arow] = x2t;
        }
        __syncthreads();

        // ---- logits into sL (stage0 A region) ----
        {
            #pragma unroll
            for (int nt = 0; nt < 2; nt++) {
                const int c = wn * 16 + nt * 8 + lk;
                const float p20 = sP2[c], p21 = sP2[c + 1];
                const float rv0 = sRv[c], rv1 = sRv[c + 1];
                const int r0 = wm * 16 + gr;
                const float x2a = sX2[r0], x2b = sX2[r0 + 8];
                const float* A = acc[nt];
                sL[r0 * SL_STR + c]           = fmaf(2.0f, A[0], -(x2a + p20)) * rv0;
                sL[r0 * SL_STR + c + 1]       = fmaf(2.0f, A[1], -(x2a + p21)) * rv1;
                sL[(r0 + 8) * SL_STR + c]     = fmaf(2.0f, A[2], -(x2b + p20)) * rv0;
                sL[(r0 + 8) * SL_STR + c + 1] = fmaf(2.0f, A[3], -(x2b + p21)) * rv1;
            }
        }
        __syncthreads();

        // ---- softmax per row (8 threads/row, 8-col stripes) ----
        {
            const float* Lr = sL + lr * SL_STR;
            float f[8];
            #pragma unroll
            for (int i = 0; i < 8; i++) f[i] = Lr[lc + i];
            const float Ly = Lr[cls];

            float mx = f[0];
            #pragma unroll
            for (int i = 1; i < 8; i++) mx = fmaxf(mx, f[i]);
            mx = fmaxf(mx, __shfl_xor_sync(0xffffffffu, mx, 1));
            mx = fmaxf(mx, __shfl_xor_sync(0xffffffffu, mx, 2));
            mx = fmaxf(mx, __shfl_xor_sync(0xffffffffu, mx, 4));

            float s = 0.0f;
            #pragma unroll
            for (int i = 0; i < 8; i++) { f[i] = __expf(f[i] - mx); s += f[i]; }
            s += __shfl_xor_sync(0xffffffffu, s, 1);
            s += __shfl_xor_sync(0xffffffffu, s, 2);
            s += __shfl_xor_sync(0xffffffffu, s, 4);

            const float winv = wts[m] / s;
            #pragma unroll
            for (int i = 0; i < 8; i++) pred[i] += f[i] * winv;

            if ((tid & 7) == (cls >> 3))
                lossAcc += -wts[m] * (Ly - mx - logf(s));
        }
        __syncthreads();
    }

    // ---- final: argmax + block reduction ----
    {
        float bv = pred[0]; int bi = lc;
        #pragma unroll
        for (int i = 1; i < 8; i++)
            if (pred[i] > bv) { bv = pred[i]; bi = lc + i; }
        #pragma unroll
        for (int o = 1; o <= 4; o <<= 1) {
            const float ov = __shfl_xor_sync(0xffffffffu, bv, o);
            const int   oi = __shfl_xor_sync(0xffffffffu, bi, o);
            if (ov > bv || (ov == bv && oi < bi)) { bv = ov; bi = oi; }
        }
        float ls = lossAcc;
        ls += __shfl_xor_sync(0xffffffffu, ls, 1);
        ls += __shfl_xor_sync(0xffffffffu, ls, 2);
        ls += __shfl_xor_sync(0xffffffffu, ls, 4);

        float lrow = ((lane & 7) == 0) ? ls : 0.0f;
        int   arw  = ((lane & 7) == 0 && bi == cls) ? 1 : 0;
        lrow += __shfl_xor_sync(0xffffffffu, lrow, 8);
        lrow += __shfl_xor_sync(0xffffffffu, lrow, 16);
        arw  += __shfl_xor_sync(0xffffffffu, arw, 8);
        arw  += __shfl_xor_sync(0xffffffffu, arw, 16);
        if (lane == 0) {
            atomicAdd(sBL, lrow);
            atomicAdd(sBA, arw);
        }
    }
    __syncthreads();
    if (tid == 0) {
        g_part[blockIdx.x] = make_float2(*sBL, (float)*sBA);
        __threadfence();
        const int v = atomicAdd(&g_done, 1);
        sLast = (v == NCTA - 1) ? 1 : 0;
    }
    __syncthreads();

    if (sLast) {
        float2 p = g_part[tid];
        float l = p.x, a = p.y;
        #pragma unroll
        for (int o = 16; o > 0; o >>= 1) {
            l += __shfl_xor_sync(0xffffffffu, l, o);
            a += __shfl_xor_sync(0xffffffffu, a, o);
        }
        float* rl = sX2;
        float* ra = sX2 + 8;
        if ((tid & 31) == 0) { rl[warp] = l; ra[warp] = a; }
        __syncthreads();
        if (tid == 0) {
            float ls = 0.0f, as = 0.0f;
            #pragma unroll
            for (int i = 0; i < 8; i++) { ls += rl[i]; as += ra[i]; }
            out[0] = ls * (1.0f / NROWS);
            if (out_size > 1) out[1] = as * (1.0f / NROWS);
            for (int i = 2; i < out_size; i++) out[i] = 0.0f;
            g_done = 0;
        }
    }
}

// ---------------------------------------------------------------------------
extern "C" void kernel_launch(void* const* d_in, const int* in_sizes, int n_in,
                              void* d_out, int out_size)
{
    (void)in_sizes; (void)n_in;
    const float* TFq  = (const float*)d_in[0];
    const float* pTF  = (const float*)d_in[1];
    const float* vTF  = (const float*)d_in[2];
    const float* DEq  = (const float*)d_in[3];
    const float* pDE  = (const float*)d_in[4];
    const float* vDE  = (const float*)d_in[5];
    const float* FFTq = (const float*)d_in[6];
    const float* pFFT = (const float*)d_in[7];
    const float* vFFT = (const float*)d_in[8];

    static int smem_set = 0;
    if (!smem_set) {
        cudaFuncSetAttribute(fusion_kernel, cudaFuncAttributeMaxDynamicSharedMemorySize, SMEM_TOTAL);
        smem_set = 1;
    }

    prep_kernel<<<192, 128>>>(pTF, vTF, pDE, vDE, pFFT, vFFT);
    fusion_kernel<<<NCTA, 256, SMEM_TOTAL>>>(TFq, DEq, FFTq, (float*)d_out, out_size);
}